// round 10
// baseline (speedup 1.0000x reference)
#include <cuda_runtime.h>
#include <cuda_bf16.h>
#include <math.h>

// ---------------------------------------------------------------------------
// Problem dims
// ---------------------------------------------------------------------------
#define C2d 32
#define C1d 64
#define Td 2048
#define AVGF 32
#define SEG 64
#define Md 2048
#define TKd 3
#define HAd 16
#define DHd 128

// scratch (no allocations allowed -> __device__ globals)
__device__ float g_altx[AVGF * Md];
__device__ float g_s[AVGF * Md];
__device__ float g_y[AVGF * Md];
__device__ float g_qkv[AVGF * 3 * Md];
__device__ float g_imv[AVGF * Md];
__device__ float g_h[AVGF * 4 * Md];
// split-K partial buffer: max = 8 * 32 * 8192 = 2,097,152 floats (8.4 MB)
__device__ float g_part[2100000];
// A in MMA-fragment layout, 2 bf16 planes: (K/16) * 128 uint4; K<=8192 -> 1MB
__device__ uint4 g_afrag[65536];

#define F_BIAS 1
#define F_RES  2
#define F_GELU 4
#define F_SIN  8

// ---------------------------------------------------------------------------
// helpers: bf16 2-plane split (hi = rn(v), lo = rn(v - hi)); k-pairs packed
// into one 32-bit word (lo half = even k, hi half = odd k).
// ---------------------------------------------------------------------------
__device__ __forceinline__ void split2(float x0, float x1, unsigned& hi, unsigned& lo) {
    asm("cvt.rn.bf16x2.f32 %0, %1, %2;" : "=r"(hi) : "f"(x1), "f"(x0));
    float h0 = __uint_as_float(hi << 16);
    float h1 = __uint_as_float(hi & 0xFFFF0000u);
    float l0 = x0 - h0;
    float l1 = x1 - h1;
    asm("cvt.rn.bf16x2.f32 %0, %1, %2;" : "=r"(lo) : "f"(l1), "f"(l0));
}

__device__ __forceinline__ void mma_bf16(float c[4], unsigned a0, unsigned a1,
                                         unsigned a2, unsigned a3,
                                         unsigned b0, unsigned b1) {
    asm volatile(
        "mma.sync.aligned.m16n8k16.row.col.f32.bf16.bf16.f32 "
        "{%0,%1,%2,%3}, {%4,%5,%6,%7}, {%8,%9}, {%0,%1,%2,%3};"
        : "+f"(c[0]), "+f"(c[1]), "+f"(c[2]), "+f"(c[3])
        : "r"(a0), "r"(a1), "r"(a2), "r"(a3), "r"(b0), "r"(b1));
}

// ---------------------------------------------------------------------------
// Kernel 1: segment average   altx[i, c1*32+c2] = mean_t x[c2, c1, i*64+t]
// ---------------------------------------------------------------------------
__global__ void avg_kernel(const float* __restrict__ x, float* __restrict__ altx) {
    int b = blockIdx.x;           // b = c2*64 + c1
    int c2 = b >> 6, c1 = b & 63;
    const float* row = x + (size_t)b * Td;
    __shared__ float ssum[AVGF];
    int tid = threadIdx.x;
    if (tid < AVGF) ssum[tid] = 0.f;
    __syncthreads();
    float local = 0.f;
    int base = tid * 8;
#pragma unroll
    for (int m = 0; m < 8; m++) local += row[base + m];
    atomicAdd(&ssum[tid >> 3], local);
    __syncthreads();
    if (tid < AVGF)
        altx[tid * Md + c1 * 32 + c2] = ssum[tid] * (1.0f / 64.0f);
}

// ---------------------------------------------------------------------------
// A-prep: convert A[32, K] fp32 into mma.m16n8k16 fragment layout, 2 planes.
// AF[s*128 + (mt*2+plane)*32 + lane] = uint4 of frag words a0..a3 for k16
// step s, m-tile mt. Word j packs k-pair (2kp, 2kp+1) as bf16x2.
// ---------------------------------------------------------------------------
__global__ void prep_afrag(const float* __restrict__ A, uint4* __restrict__ AF, int K) {
    int idx = blockIdx.x * blockDim.x + threadIdx.x;
    int total = (K >> 4) << 6;             // (K/16) * 64 threads
    if (idx >= total) return;
    int lane = idx & 31;
    int mt = (idx >> 5) & 1;
    int s = idx >> 6;
    int m = mt * 16 + (lane >> 2);
    int k0 = s * 16 + (lane & 3) * 2;

    float2 a  = *(const float2*)&A[m * K + k0];
    float2 b  = *(const float2*)&A[(m + 8) * K + k0];
    float2 cc = *(const float2*)&A[m * K + k0 + 8];
    float2 d  = *(const float2*)&A[(m + 8) * K + k0 + 8];

    unsigned h0, l0, h1, l1, h2, l2, h3, l3;
    split2(a.x, a.y, h0, l0);
    split2(b.x, b.y, h1, l1);
    split2(cc.x, cc.y, h2, l2);
    split2(d.x, d.y, h3, l3);

    AF[(size_t)s * 128 + (mt * 2 + 0) * 32 + lane] = make_uint4(h0, h1, h2, h3);
    AF[(size_t)s * 128 + (mt * 2 + 1) * 32 + lane] = make_uint4(l0, l1, l2, l3);
}

// ---------------------------------------------------------------------------
// Split-K skinny GEMM v2 — NO shared memory, NO __syncthreads.
//   PART[ky, 32, N] = A[32, kslice] @ W[N, kslice]^T
// 128 threads / 4 warps; warp w owns output cols [bx*64 + 16w, +16).
// A fragments come pre-converted from AF (L1/L2-hot, same addr all warps).
// B fragments are built in-register from aligned LDG.64 of W + split2.
// D = ah*bh + ah*bl + al*bh per k16 step (12 MMAs/warp/step).
// ---------------------------------------------------------------------------
template<int SPLITK>
__global__ void __launch_bounds__(128, 5)
gemm_v2(const uint4* __restrict__ AF, const float* __restrict__ W,
        float* __restrict__ PART, int N, int K)
{
    const int tid  = threadIdx.x;
    const int lane = tid & 31;
    const int warp = tid >> 5;
    const int gid  = lane >> 2;   // 0..7
    const int tig  = lane & 3;    // 0..3

    const int n0    = blockIdx.x * 64 + warp * 16;
    const int steps = (K >> 4) / SPLITK;
    const int s0    = blockIdx.y * steps;

    const float* bp0 = W + (size_t)(n0 + gid) * K;       // n8 group 0
    const float* bp1 = W + (size_t)(n0 + 8 + gid) * K;   // n8 group 1
    const int kb = s0 * 16 + tig * 2;

    // software pipeline registers for raw fp32 B
    float2 b0a, b0b, b1a, b1b, x0a, x0b, x1a, x1b;
    b0a = *(const float2*)&bp0[kb];
    b0b = *(const float2*)&bp0[kb + 8];
    b1a = *(const float2*)&bp1[kb];
    b1b = *(const float2*)&bp1[kb + 8];

    float c[2][2][4] = {};

    for (int s = 0; s < steps; s++) {
        if (s + 1 < steps) {
            int kn = kb + (s + 1) * 16;
            x0a = *(const float2*)&bp0[kn];
            x0b = *(const float2*)&bp0[kn + 8];
            x1a = *(const float2*)&bp1[kn];
            x1b = *(const float2*)&bp1[kn + 8];
        }
        // A fragments (identical addresses across warps -> L1 broadcast)
        const uint4* af = AF + (size_t)(s0 + s) * 128;
        uint4 ah0 = af[lane];
        uint4 al0 = af[32 + lane];
        uint4 ah1 = af[64 + lane];
        uint4 al1 = af[96 + lane];

        // B conversion in-register
        unsigned bh00, bl00, bh01, bl01, bh10, bl10, bh11, bl11;
        split2(b0a.x, b0a.y, bh00, bl00);
        split2(b0b.x, b0b.y, bh01, bl01);
        split2(b1a.x, b1a.y, bh10, bl10);
        split2(b1b.x, b1b.y, bh11, bl11);

        // t8 = 0
        mma_bf16(c[0][0], ah0.x, ah0.y, ah0.z, ah0.w, bh00, bh01);
        mma_bf16(c[0][0], ah0.x, ah0.y, ah0.z, ah0.w, bl00, bl01);
        mma_bf16(c[0][0], al0.x, al0.y, al0.z, al0.w, bh00, bh01);
        mma_bf16(c[1][0], ah1.x, ah1.y, ah1.z, ah1.w, bh00, bh01);
        mma_bf16(c[1][0], ah1.x, ah1.y, ah1.z, ah1.w, bl00, bl01);
        mma_bf16(c[1][0], al1.x, al1.y, al1.z, al1.w, bh00, bh01);
        // t8 = 1
        mma_bf16(c[0][1], ah0.x, ah0.y, ah0.z, ah0.w, bh10, bh11);
        mma_bf16(c[0][1], ah0.x, ah0.y, ah0.z, ah0.w, bl10, bl11);
        mma_bf16(c[0][1], al0.x, al0.y, al0.z, al0.w, bh10, bh11);
        mma_bf16(c[1][1], ah1.x, ah1.y, ah1.z, ah1.w, bh10, bh11);
        mma_bf16(c[1][1], ah1.x, ah1.y, ah1.z, ah1.w, bl10, bl11);
        mma_bf16(c[1][1], al1.x, al1.y, al1.z, al1.w, bh10, bh11);

        b0a = x0a; b0b = x0b; b1a = x1a; b1b = x1b;
    }

    // write partials: c[mt][t8] -> rows mt*16+gid(+8), cols n0+t8*8+2*tig
    float* base = &PART[(size_t)blockIdx.y * 32 * N];
#pragma unroll
    for (int mt = 0; mt < 2; mt++)
#pragma unroll
        for (int t8 = 0; t8 < 2; t8++) {
            int col = n0 + t8 * 8 + 2 * tig;
            int r0  = mt * 16 + gid;
            *(float2*)&base[r0 * N + col]       = make_float2(c[mt][t8][0], c[mt][t8][1]);
            *(float2*)&base[(r0 + 8) * N + col] = make_float2(c[mt][t8][2], c[mt][t8][3]);
        }
}

// ---------------------------------------------------------------------------
// block-wide sum (256 threads)
// ---------------------------------------------------------------------------
__device__ __forceinline__ float block_sum(float v, float* sh) {
#pragma unroll
    for (int o = 16; o; o >>= 1) v += __shfl_xor_sync(0xFFFFFFFFu, v, o);
    int w = threadIdx.x >> 5;
    if ((threadIdx.x & 31) == 0) sh[w] = v;
    __syncthreads();
    float r = 0.f;
    if (threadIdx.x < 32) {
        r = (threadIdx.x < 8) ? sh[threadIdx.x] : 0.f;
#pragma unroll
        for (int o = 4; o; o >>= 1) r += __shfl_xor_sync(0xFFFFFFFFu, r, o);
    }
    if (threadIdx.x == 0) sh[0] = r;
    __syncthreads();
    float out = sh[0];
    __syncthreads();
    return out;
}

// ---------------------------------------------------------------------------
// Fused split-K reduce + epilogue + LayerNorm for N=2048.
// One block per row (32 blocks, 256 threads, 8 elems/thread).
// LNMODE: 0 = write OUT_s = v only
//         1 = write OUT_s = v  and  OUT_y = LN(v)*g+b          (ln1)
//         2 = write OUT_s = LN(v)*g+b + v                      (ln2 + residual)
// ---------------------------------------------------------------------------
template<int SPLITK, int FLAGS, int LNMODE>
__global__ void reduce_ln(const float* __restrict__ PART, const float* __restrict__ bias,
                          const float* __restrict__ resid, float* __restrict__ OUT_s,
                          float* __restrict__ OUT_y, const float* __restrict__ g,
                          const float* __restrict__ bp)
{
    __shared__ float sh[8];
    const int r = blockIdx.x, tid = threadIdx.x;
    const int c0 = tid * 8;

    float o[8] = {0.f, 0.f, 0.f, 0.f, 0.f, 0.f, 0.f, 0.f};
#pragma unroll
    for (int p = 0; p < SPLITK; p++) {
        const float* b = &PART[((size_t)p * 32 + r) * Md + c0];
        float4 x0 = *(const float4*)b;
        float4 x1 = *(const float4*)(b + 4);
        o[0] += x0.x; o[1] += x0.y; o[2] += x0.z; o[3] += x0.w;
        o[4] += x1.x; o[5] += x1.y; o[6] += x1.z; o[7] += x1.w;
    }
    if (FLAGS & F_BIAS) {
        float4 b0 = *(const float4*)&bias[c0];
        float4 b1 = *(const float4*)&bias[c0 + 4];
        o[0] += b0.x; o[1] += b0.y; o[2] += b0.z; o[3] += b0.w;
        o[4] += b1.x; o[5] += b1.y; o[6] += b1.z; o[7] += b1.w;
    }
    if (FLAGS & F_SIN) {
#pragma unroll
        for (int j = 0; j < 8; j++) {
            int cc = c0 + j;
            int e = cc & ~1;
            float ang = (float)r * powf(10000.0f, -(float)e * (1.0f / 1024.0f));
            o[j] += (cc & 1) ? cosf(ang) : sinf(ang);
        }
    }
    if (FLAGS & F_RES) {
        const float* b = &resid[r * Md + c0];
        float4 x0 = *(const float4*)b;
        float4 x1 = *(const float4*)(b + 4);
        o[0] += x0.x; o[1] += x0.y; o[2] += x0.z; o[3] += x0.w;
        o[4] += x1.x; o[5] += x1.y; o[6] += x1.z; o[7] += x1.w;
    }

    if (LNMODE == 0) {
        *(float4*)&OUT_s[r * Md + c0]     = make_float4(o[0], o[1], o[2], o[3]);
        *(float4*)&OUT_s[r * Md + c0 + 4] = make_float4(o[4], o[5], o[6], o[7]);
        return;
    }

    float s = 0.f;
#pragma unroll
    for (int j = 0; j < 8; j++) s += o[j];
    float mean = block_sum(s, sh) * (1.0f / (float)Md);
    float sq = 0.f;
#pragma unroll
    for (int j = 0; j < 8; j++) { float d = o[j] - mean; sq += d * d; }
    float var = block_sum(sq, sh) * (1.0f / (float)Md);
    float rstd = rsqrtf(var + 1e-5f);

    float yv[8];
#pragma unroll
    for (int j = 0; j < 8; j++)
        yv[j] = (o[j] - mean) * rstd * g[c0 + j] + bp[c0 + j];

    if (LNMODE == 1) {
        *(float4*)&OUT_s[r * Md + c0]     = make_float4(o[0], o[1], o[2], o[3]);
        *(float4*)&OUT_s[r * Md + c0 + 4] = make_float4(o[4], o[5], o[6], o[7]);
        *(float4*)&OUT_y[r * Md + c0]     = make_float4(yv[0], yv[1], yv[2], yv[3]);
        *(float4*)&OUT_y[r * Md + c0 + 4] = make_float4(yv[4], yv[5], yv[6], yv[7]);
    } else { // LNMODE == 2
#pragma unroll
        for (int j = 0; j < 8; j++) yv[j] += o[j];
        *(float4*)&OUT_s[r * Md + c0]     = make_float4(yv[0], yv[1], yv[2], yv[3]);
        *(float4*)&OUT_s[r * Md + c0 + 4] = make_float4(yv[4], yv[5], yv[6], yv[7]);
    }
}

// ---------------------------------------------------------------------------
// Elementwise split-K reduction (for N=6144 / N=8192) + optional bias/gelu
// ---------------------------------------------------------------------------
template<int SPLITK, int FLAGS>
__global__ void reduce_ep(const float* __restrict__ PART, const float* __restrict__ bias,
                          float* __restrict__ OUT, int N)
{
    int idx = blockIdx.x * blockDim.x + threadIdx.x;
    int n4 = N >> 2;
    if (idx >= 32 * n4) return;
    int r = idx / n4;
    int c = (idx - r * n4) * 4;

    float o[4] = {0.f, 0.f, 0.f, 0.f};
#pragma unroll
    for (int p = 0; p < SPLITK; p++) {
        float4 v = *(const float4*)&PART[((size_t)p * 32 + r) * N + c];
        o[0] += v.x; o[1] += v.y; o[2] += v.z; o[3] += v.w;
    }
    if (FLAGS & F_BIAS) {
        float4 b = *(const float4*)&bias[c];
        o[0] += b.x; o[1] += b.y; o[2] += b.z; o[3] += b.w;
    }
    if (FLAGS & F_GELU) {
#pragma unroll
        for (int j = 0; j < 4; j++)
            o[j] = 0.5f * o[j] * (1.0f + erff(o[j] * 0.70710678118654752f));
    }
    *(float4*)&OUT[r * N + c] = make_float4(o[0], o[1], o[2], o[3]);
}

// ---------------------------------------------------------------------------
// Scalar attention + serial cumsum.
// Phase 1: warp-per-token rsa (no block syncs). Phase 2: sync-free cumsum
// loop -> all 32 v-loads pipeline (deep MLP) behind the serial FADD chain.
// ---------------------------------------------------------------------------
__global__ void attn_kernel(const float* __restrict__ qkv, float* __restrict__ imv) {
    __shared__ float srsa[AVGF];
    int h = blockIdx.x, tid = threadIdx.x;
    int lane = tid & 31, warp = tid >> 5;
    const float inv = 0.088388347648318447f; // 1/sqrt(128)

    // phase 1: rsa[i] for i = 4*ii + warp
#pragma unroll
    for (int ii = 0; ii < 8; ii++) {
        int i = ii * 4 + warp;
        const float* qp = qkv + i * (3 * Md) + h * DHd;
        float p = 0.f;
#pragma unroll
        for (int j = 0; j < 4; j++) {
            float q = qp[lane + 32 * j];
            float k = qp[Md + lane + 32 * j];
            p = fmaf(q, k, p);
        }
#pragma unroll
        for (int o = 16; o; o >>= 1) p += __shfl_xor_sync(0xFFFFFFFFu, p, o);
        if (lane == 0) srsa[i] = p * inv;
    }
    __syncthreads();

    // phase 2: serial cumsum over tokens (no syncs in loop)
    int d = tid;   // 0..127
    float run = 0.f;
#pragma unroll
    for (int i = 0; i < AVGF; i++) {
        run = fmaf(srsa[i], qkv[i * (3 * Md) + 2 * Md + h * DHd + d], run);
        imv[i * Md + h * DHd + d] = run;
    }
}

// ---------------------------------------------------------------------------
// launch
// ---------------------------------------------------------------------------
extern "C" void kernel_launch(void* const* d_in, const int* in_sizes, int n_in,
                              void* d_out, int out_size) {
    const float* x      = (const float*)d_in[0];
    const float* weight = (const float*)d_in[1];
    const float* Wqkv   = (const float*)d_in[2];
    const float* Wo     = (const float*)d_in[3];
    const float* ln1_g  = (const float*)d_in[4];
    const float* ln1_b  = (const float*)d_in[5];
    const float* ln2_g  = (const float*)d_in[6];
    const float* ln2_b  = (const float*)d_in[7];
    const float* fc1_w  = (const float*)d_in[8];
    const float* fc1_b  = (const float*)d_in[9];
    const float* fc2_w  = (const float*)d_in[10];
    const float* fc2_b  = (const float*)d_in[11];
    float* out = (float*)d_out;

    float *altx, *s, *y, *qkv, *imv, *hbuf, *part;
    uint4* afrag;
    cudaGetSymbolAddress((void**)&altx,  g_altx);
    cudaGetSymbolAddress((void**)&s,     g_s);
    cudaGetSymbolAddress((void**)&y,     g_y);
    cudaGetSymbolAddress((void**)&qkv,   g_qkv);
    cudaGetSymbolAddress((void**)&imv,   g_imv);
    cudaGetSymbolAddress((void**)&hbuf,  g_h);
    cudaGetSymbolAddress((void**)&part,  g_part);
    cudaGetSymbolAddress((void**)&afrag, g_afrag);

    auto rgrid = [](int N) { return (32 * (N / 4) + 127) / 128; };
    auto pgrid = [](int K) { return ((K / 16) * 64 + 255) / 256; };

    // 1) segment average
    avg_kernel<<<C2d * C1d, 256>>>(x, altx);

    // 2) s = altx @ weight^T + sin bias; y = LN1(s)   (N=2048, K=2048)
    prep_afrag<<<pgrid(Md), 256>>>(altx, afrag, Md);
    gemm_v2<16><<<dim3(Md / 64, 16), 128>>>(afrag, weight, part, Md, Md);
    reduce_ln<16, F_SIN, 1><<<AVGF, 256>>>(part, nullptr, nullptr, s, y, ln1_g, ln1_b);

    for (int a = 0; a < TKd; a++) {
        // qkv = y @ Wqkv[a]^T      (N=6144, K=2048, splitK=8 -> 768 blocks)
        prep_afrag<<<pgrid(Md), 256>>>(y, afrag, Md);
        gemm_v2<8><<<dim3((3 * Md) / 64, 8), 128>>>(
            afrag, Wqkv + (size_t)a * 3 * Md * Md, part, 3 * Md, Md);
        reduce_ep<8, 0><<<rgrid(3 * Md), 128>>>(part, nullptr, qkv, 3 * Md);

        // scalar attention + cumsum
        attn_kernel<<<HAd, DHd>>>(qkv, imv);

        // s' = imv @ Wo[a]^T + s;  s = LN2(s') + s'   (N=2048, K=2048, splitK=16)
        prep_afrag<<<pgrid(Md), 256>>>(imv, afrag, Md);
        gemm_v2<16><<<dim3(Md / 64, 16), 128>>>(
            afrag, Wo + (size_t)a * Md * Md, part, Md, Md);
        reduce_ln<16, F_RES, 2><<<AVGF, 256>>>(part, nullptr, s, s, nullptr, ln2_g, ln2_b);

        // h = gelu(s @ fc1^T + b)  (N=8192, K=2048, splitK=8 -> 1024 blocks)
        prep_afrag<<<pgrid(Md), 256>>>(s, afrag, Md);
        gemm_v2<8><<<dim3((4 * Md) / 64, 8), 128>>>(afrag, fc1_w, part, 4 * Md, Md);
        reduce_ep<8, F_BIAS | F_GELU><<<rgrid(4 * Md), 128>>>(part, fc1_b, hbuf, 4 * Md);

        // s = h @ fc2^T + b        (N=2048, K=8192, splitK=16 -> 512 blocks)
        prep_afrag<<<pgrid(4 * Md), 256>>>(hbuf, afrag, 4 * Md);
        gemm_v2<16><<<dim3(Md / 64, 16), 128>>>(afrag, fc2_w, part, Md, 4 * Md);
        if (a < TKd - 1) {
            // fuse next block's LN1: write s and y
            reduce_ln<16, F_BIAS, 1><<<AVGF, 256>>>(part, fc2_b, nullptr, s, y,
                                                    ln1_g, ln1_b);
        } else {
            reduce_ln<16, F_BIAS, 0><<<AVGF, 256>>>(part, fc2_b, nullptr, out, nullptr,
                                                    nullptr, nullptr);
        }
    }
}

// round 13
// speedup vs baseline: 1.0287x; 1.0287x over previous
#include <cuda_runtime.h>
#include <cuda_bf16.h>
#include <math.h>

// ---------------------------------------------------------------------------
// Problem dims
// ---------------------------------------------------------------------------
#define C2d 32
#define C1d 64
#define Td 2048
#define AVGF 32
#define SEG 64
#define Md 2048
#define TKd 3
#define HAd 16
#define DHd 128

// scratch (no allocations allowed -> __device__ globals)
__device__ float g_altx[AVGF * Md];
__device__ float g_s[AVGF * Md];
// split-K partial buffer: max = 8 * 32 * 8192 = 2,097,152 floats (8.4 MB)
__device__ float g_part[2100000];
// A in MMA-fragment layout, 2 bf16 planes: (K/16) * 128 uint4; K<=8192 -> 1MB
__device__ uint4 g_afrag[65536];

#define F_BIAS 1
#define F_RES  2
#define F_GELU 4
#define F_SIN  8

// ---------------------------------------------------------------------------
// helpers: bf16 2-plane split (hi = rn(v), lo = rn(v - hi)); k-pairs packed
// into one 32-bit word (lo half = even k, hi half = odd k).
// ---------------------------------------------------------------------------
__device__ __forceinline__ void split2(float x0, float x1, unsigned& hi, unsigned& lo) {
    asm("cvt.rn.bf16x2.f32 %0, %1, %2;" : "=r"(hi) : "f"(x1), "f"(x0));
    float h0 = __uint_as_float(hi << 16);
    float h1 = __uint_as_float(hi & 0xFFFF0000u);
    float l0 = x0 - h0;
    float l1 = x1 - h1;
    asm("cvt.rn.bf16x2.f32 %0, %1, %2;" : "=r"(lo) : "f"(l1), "f"(l0));
}

__device__ __forceinline__ void mma_bf16(float c[4], unsigned a0, unsigned a1,
                                         unsigned a2, unsigned a3,
                                         unsigned b0, unsigned b1) {
    asm volatile(
        "mma.sync.aligned.m16n8k16.row.col.f32.bf16.bf16.f32 "
        "{%0,%1,%2,%3}, {%4,%5,%6,%7}, {%8,%9}, {%0,%1,%2,%3};"
        : "+f"(c[0]), "+f"(c[1]), "+f"(c[2]), "+f"(c[3])
        : "r"(a0), "r"(a1), "r"(a2), "r"(a3), "r"(b0), "r"(b1));
}

// Store one (m, k-pair) of a [32,K] activation into the fragment layout that
// gemm_v2 reads. Inverse of prep_afrag's map:
//   word index = (s*128 + (mt*2+plane)*32 + lane)*4 + j
//   lane = (m&7)*4 + (k&7)/2 ; j = 2*[ (k%16)>=8 ] + [ (m%16)>=8 ]
__device__ __forceinline__ void st_afrag(unsigned* AF, int m, int k,
                                         unsigned hi, unsigned lo) {
    int s    = k >> 4;
    int mt   = m >> 4;
    int lane = (m & 7) * 4 + ((k & 7) >> 1);
    int j    = (((k & 15) >= 8) ? 2 : 0) + (((m & 15) >= 8) ? 1 : 0);
    unsigned* base = AF + (size_t)(s * 128 + mt * 64) * 4;
    base[lane * 4 + j]        = hi;   // plane 0
    base[(32 + lane) * 4 + j] = lo;   // plane 1
}

// ---------------------------------------------------------------------------
// Kernel 1: segment average   altx[i, c1*32+c2] = mean_t x[c2, c1, i*64+t]
// ---------------------------------------------------------------------------
__global__ void avg_kernel(const float* __restrict__ x, float* __restrict__ altx) {
    int b = blockIdx.x;           // b = c2*64 + c1
    int c2 = b >> 6, c1 = b & 63;
    const float* row = x + (size_t)b * Td;
    __shared__ float ssum[AVGF];
    int tid = threadIdx.x;
    if (tid < AVGF) ssum[tid] = 0.f;
    __syncthreads();
    float local = 0.f;
    int base = tid * 8;
#pragma unroll
    for (int m = 0; m < 8; m++) local += row[base + m];
    atomicAdd(&ssum[tid >> 3], local);
    __syncthreads();
    if (tid < AVGF)
        altx[tid * Md + c1 * 32 + c2] = ssum[tid] * (1.0f / 64.0f);
}

// ---------------------------------------------------------------------------
// A-prep (used once, for altx): A[32,K] fp32 -> fragment layout, 2 planes.
// ---------------------------------------------------------------------------
__global__ void prep_afrag(const float* __restrict__ A, uint4* __restrict__ AF, int K) {
    int idx = blockIdx.x * blockDim.x + threadIdx.x;
    int total = (K >> 4) << 6;             // (K/16) * 64 threads
    if (idx >= total) return;
    int lane = idx & 31;
    int mt = (idx >> 5) & 1;
    int s = idx >> 6;
    int m = mt * 16 + (lane >> 2);
    int k0 = s * 16 + (lane & 3) * 2;

    float2 a  = *(const float2*)&A[m * K + k0];
    float2 b  = *(const float2*)&A[(m + 8) * K + k0];
    float2 cc = *(const float2*)&A[m * K + k0 + 8];
    float2 d  = *(const float2*)&A[(m + 8) * K + k0 + 8];

    unsigned h0, l0, h1, l1, h2, l2, h3, l3;
    split2(a.x, a.y, h0, l0);
    split2(b.x, b.y, h1, l1);
    split2(cc.x, cc.y, h2, l2);
    split2(d.x, d.y, h3, l3);

    AF[(size_t)s * 128 + (mt * 2 + 0) * 32 + lane] = make_uint4(h0, h1, h2, h3);
    AF[(size_t)s * 128 + (mt * 2 + 1) * 32 + lane] = make_uint4(l0, l1, l2, l3);
}

// ---------------------------------------------------------------------------
// Split-K skinny GEMM — NO shared memory, NO __syncthreads.
//   PART[ky, 32, N] = A[32, kslice] @ W[N, kslice]^T
// ---------------------------------------------------------------------------
template<int SPLITK>
__global__ void __launch_bounds__(128, 5)
gemm_v2(const uint4* __restrict__ AF, const float* __restrict__ W,
        float* __restrict__ PART, int N, int K)
{
    const int tid  = threadIdx.x;
    const int lane = tid & 31;
    const int warp = tid >> 5;
    const int gid  = lane >> 2;   // 0..7
    const int tig  = lane & 3;    // 0..3

    const int n0    = blockIdx.x * 64 + warp * 16;
    const int steps = (K >> 4) / SPLITK;
    const int s0    = blockIdx.y * steps;

    const float* bp0 = W + (size_t)(n0 + gid) * K;       // n8 group 0
    const float* bp1 = W + (size_t)(n0 + 8 + gid) * K;   // n8 group 1
    const int kb = s0 * 16 + tig * 2;

    float2 b0a, b0b, b1a, b1b, x0a, x0b, x1a, x1b;
    b0a = *(const float2*)&bp0[kb];
    b0b = *(const float2*)&bp0[kb + 8];
    b1a = *(const float2*)&bp1[kb];
    b1b = *(const float2*)&bp1[kb + 8];

    float c[2][2][4] = {};

    for (int s = 0; s < steps; s++) {
        if (s + 1 < steps) {
            int kn = kb + (s + 1) * 16;
            x0a = *(const float2*)&bp0[kn];
            x0b = *(const float2*)&bp0[kn + 8];
            x1a = *(const float2*)&bp1[kn];
            x1b = *(const float2*)&bp1[kn + 8];
        }
        const uint4* af = AF + (size_t)(s0 + s) * 128;
        uint4 ah0 = af[lane];
        uint4 al0 = af[32 + lane];
        uint4 ah1 = af[64 + lane];
        uint4 al1 = af[96 + lane];

        unsigned bh00, bl00, bh01, bl01, bh10, bl10, bh11, bl11;
        split2(b0a.x, b0a.y, bh00, bl00);
        split2(b0b.x, b0b.y, bh01, bl01);
        split2(b1a.x, b1a.y, bh10, bl10);
        split2(b1b.x, b1b.y, bh11, bl11);

        mma_bf16(c[0][0], ah0.x, ah0.y, ah0.z, ah0.w, bh00, bh01);
        mma_bf16(c[0][0], ah0.x, ah0.y, ah0.z, ah0.w, bl00, bl01);
        mma_bf16(c[0][0], al0.x, al0.y, al0.z, al0.w, bh00, bh01);
        mma_bf16(c[1][0], ah1.x, ah1.y, ah1.z, ah1.w, bh00, bh01);
        mma_bf16(c[1][0], ah1.x, ah1.y, ah1.z, ah1.w, bl00, bl01);
        mma_bf16(c[1][0], al1.x, al1.y, al1.z, al1.w, bh00, bh01);
        mma_bf16(c[0][1], ah0.x, ah0.y, ah0.z, ah0.w, bh10, bh11);
        mma_bf16(c[0][1], ah0.x, ah0.y, ah0.z, ah0.w, bl10, bl11);
        mma_bf16(c[0][1], al0.x, al0.y, al0.z, al0.w, bh10, bh11);
        mma_bf16(c[1][1], ah1.x, ah1.y, ah1.z, ah1.w, bh10, bh11);
        mma_bf16(c[1][1], ah1.x, ah1.y, ah1.z, ah1.w, bl10, bl11);
        mma_bf16(c[1][1], al1.x, al1.y, al1.z, al1.w, bh10, bh11);

        b0a = x0a; b0b = x0b; b1a = x1a; b1b = x1b;
    }

    float* base = &PART[(size_t)blockIdx.y * 32 * N];
#pragma unroll
    for (int mt = 0; mt < 2; mt++)
#pragma unroll
        for (int t8 = 0; t8 < 2; t8++) {
            int col = n0 + t8 * 8 + 2 * tig;
            int r0  = mt * 16 + gid;
            *(float2*)&base[r0 * N + col]       = make_float2(c[mt][t8][0], c[mt][t8][1]);
            *(float2*)&base[(r0 + 8) * N + col] = make_float2(c[mt][t8][2], c[mt][t8][3]);
        }
}

// ---------------------------------------------------------------------------
// block-wide sum for 512 threads
// ---------------------------------------------------------------------------
__device__ __forceinline__ float block_sum512(float v, float* sh) {
#pragma unroll
    for (int o = 16; o; o >>= 1) v += __shfl_xor_sync(0xFFFFFFFFu, v, o);
    int w = threadIdx.x >> 5;
    if ((threadIdx.x & 31) == 0) sh[w] = v;
    __syncthreads();
    float r = 0.f;
    if (threadIdx.x < 32) {
        r = (threadIdx.x < 16) ? sh[threadIdx.x] : 0.f;
#pragma unroll
        for (int o = 8; o; o >>= 1) r += __shfl_xor_sync(0xFFFFFFFFu, r, o);
    }
    if (threadIdx.x == 0) sh[0] = r;
    __syncthreads();
    float out = sh[0];
    __syncthreads();
    return out;
}

// ---------------------------------------------------------------------------
// Fused split-K reduce + epilogue + LayerNorm for N=2048. 32 blocks x 512.
// LNMODE: 0 = write OUT_s = v only (final output)
//         1 = write OUT_s = v (raw) and afrag( LN(v)*g+b )          (ln1)
//         2 = write afrag( LN(v)*g+b + v ) only                     (ln2+res)
// ---------------------------------------------------------------------------
template<int SPLITK, int FLAGS, int LNMODE>
__global__ void reduce_ln(const float* __restrict__ PART, const float* __restrict__ bias,
                          const float* __restrict__ resid, float* __restrict__ OUT_s,
                          unsigned* __restrict__ AF, const float* __restrict__ g,
                          const float* __restrict__ bp)
{
    __shared__ float sh[16];
    const int r = blockIdx.x, tid = threadIdx.x;
    const int c0 = tid * 4;

    float o[4] = {0.f, 0.f, 0.f, 0.f};
#pragma unroll
    for (int p = 0; p < SPLITK; p++) {
        float4 x0 = *(const float4*)&PART[((size_t)p * 32 + r) * Md + c0];
        o[0] += x0.x; o[1] += x0.y; o[2] += x0.z; o[3] += x0.w;
    }
    if (FLAGS & F_BIAS) {
        float4 b0 = *(const float4*)&bias[c0];
        o[0] += b0.x; o[1] += b0.y; o[2] += b0.z; o[3] += b0.w;
    }
    if (FLAGS & F_SIN) {
#pragma unroll
        for (int j = 0; j < 4; j++) {
            int cc = c0 + j;
            int e = cc & ~1;
            float ang = (float)r * powf(10000.0f, -(float)e * (1.0f / 1024.0f));
            o[j] += (cc & 1) ? cosf(ang) : sinf(ang);
        }
    }
    if (FLAGS & F_RES) {
        float4 x0 = *(const float4*)&resid[r * Md + c0];
        o[0] += x0.x; o[1] += x0.y; o[2] += x0.z; o[3] += x0.w;
    }

    if (LNMODE == 0) {
        *(float4*)&OUT_s[r * Md + c0] = make_float4(o[0], o[1], o[2], o[3]);
        return;
    }

    float s = o[0] + o[1] + o[2] + o[3];
    float mean = block_sum512(s, sh) * (1.0f / (float)Md);
    float sq = 0.f;
#pragma unroll
    for (int j = 0; j < 4; j++) { float d = o[j] - mean; sq += d * d; }
    float var = block_sum512(sq, sh) * (1.0f / (float)Md);
    float rstd = rsqrtf(var + 1e-5f);

    float yv[4];
#pragma unroll
    for (int j = 0; j < 4; j++)
        yv[j] = (o[j] - mean) * rstd * g[c0 + j] + bp[c0 + j];

    if (LNMODE == 1) {
        *(float4*)&OUT_s[r * Md + c0] = make_float4(o[0], o[1], o[2], o[3]);
    } else { // LNMODE == 2
#pragma unroll
        for (int j = 0; j < 4; j++) yv[j] += o[j];
    }
    unsigned h0, l0, h1, l1;
    split2(yv[0], yv[1], h0, l0);
    split2(yv[2], yv[3], h1, l1);
    st_afrag(AF, r, c0, h0, l0);
    st_afrag(AF, r, c0 + 2, h1, l1);
}

// ---------------------------------------------------------------------------
// Split-K reduce + bias + GELU -> fragment layout only (FC1 output, N=8192)
// ---------------------------------------------------------------------------
template<int SPLITK>
__global__ void reduce_gelu_frag(const float* __restrict__ PART,
                                 const float* __restrict__ bias,
                                 unsigned* __restrict__ AF, int N)
{
    int idx = blockIdx.x * blockDim.x + threadIdx.x;
    int n4 = N >> 2;
    if (idx >= 32 * n4) return;
    int r = idx / n4;
    int c = (idx - r * n4) * 4;

    float o[4] = {0.f, 0.f, 0.f, 0.f};
#pragma unroll
    for (int p = 0; p < SPLITK; p++) {
        float4 v = *(const float4*)&PART[((size_t)p * 32 + r) * N + c];
        o[0] += v.x; o[1] += v.y; o[2] += v.z; o[3] += v.w;
    }
    float4 b = *(const float4*)&bias[c];
    o[0] += b.x; o[1] += b.y; o[2] += b.z; o[3] += b.w;
#pragma unroll
    for (int j = 0; j < 4; j++)
        o[j] = 0.5f * o[j] * (1.0f + erff(o[j] * 0.70710678118654752f));

    unsigned h0, l0, h1, l1;
    split2(o[0], o[1], h0, l0);
    split2(o[2], o[3], h1, l1);
    st_afrag(AF, r, c, h0, l0);
    st_afrag(AF, r, c + 2, h1, l1);
}

// ---------------------------------------------------------------------------
// Fused: QKV split-K reduction + scalar attention + serial cumsum.
// Reads QKV partials (SPLITK slices of [32, 6144]) directly; writes the
// imv activation straight into fragment layout for the Wo GEMM.
// grid = 16 heads, 128 threads.
// ---------------------------------------------------------------------------
template<int SPLITK>
__global__ void attn_fused(const float* __restrict__ PART, unsigned* __restrict__ AF) {
    __shared__ float srsa[AVGF];
    int h = blockIdx.x, tid = threadIdx.x;
    int lane = tid & 31, warp = tid >> 5;
    const float inv = 0.088388347648318447f; // 1/sqrt(128)

    // phase 1: rsa[i] for i = 4*ii + warp (q.k with inline split-K sum)
#pragma unroll
    for (int ii = 0; ii < 8; ii++) {
        int i = ii * 4 + warp;
        float p = 0.f;
#pragma unroll
        for (int j = 0; j < 4; j++) {
            int colq = h * DHd + lane + 32 * j;
            float qv = 0.f, kv = 0.f;
#pragma unroll
            for (int pp = 0; pp < SPLITK; pp++) {
                const float* row = &PART[((size_t)pp * 32 + i) * (3 * Md)];
                qv += row[colq];
                kv += row[Md + colq];
            }
            p = fmaf(qv, kv, p);
        }
#pragma unroll
        for (int o = 16; o; o >>= 1) p += __shfl_xor_sync(0xFFFFFFFFu, p, o);
        if (lane == 0) srsa[i] = p * inv;
    }
    __syncthreads();

    // phase 2: threads 0..63 each own a d-pair; serial cumsum, frag store
    if (tid < 64) {
        int colv = 2 * Md + h * DHd + tid * 2;
        float run0 = 0.f, run1 = 0.f;
#pragma unroll
        for (int i = 0; i < AVGF; i++) {
            float v0 = 0.f, v1 = 0.f;
#pragma unroll
            for (int pp = 0; pp < SPLITK; pp++) {
                float2 vv = *(const float2*)&PART[((size_t)pp * 32 + i) * (3 * Md) + colv];
                v0 += vv.x; v1 += vv.y;
            }
            run0 = fmaf(srsa[i], v0, run0);
            run1 = fmaf(srsa[i], v1, run1);
            unsigned hi, lo;
            split2(run0, run1, hi, lo);
            st_afrag(AF, i, h * DHd + tid * 2, hi, lo);
        }
    }
}

// ---------------------------------------------------------------------------
// launch
// ---------------------------------------------------------------------------
extern "C" void kernel_launch(void* const* d_in, const int* in_sizes, int n_in,
                              void* d_out, int out_size) {
    const float* x      = (const float*)d_in[0];
    const float* weight = (const float*)d_in[1];
    const float* Wqkv   = (const float*)d_in[2];
    const float* Wo     = (const float*)d_in[3];
    const float* ln1_g  = (const float*)d_in[4];
    const float* ln1_b  = (const float*)d_in[5];
    const float* ln2_g  = (const float*)d_in[6];
    const float* ln2_b  = (const float*)d_in[7];
    const float* fc1_w  = (const float*)d_in[8];
    const float* fc1_b  = (const float*)d_in[9];
    const float* fc2_w  = (const float*)d_in[10];
    const float* fc2_b  = (const float*)d_in[11];
    float* out = (float*)d_out;

    float *altx, *s, *part;
    uint4* afrag;
    cudaGetSymbolAddress((void**)&altx,  g_altx);
    cudaGetSymbolAddress((void**)&s,     g_s);
    cudaGetSymbolAddress((void**)&part,  g_part);
    cudaGetSymbolAddress((void**)&afrag, g_afrag);
    unsigned* afw = (unsigned*)afrag;

    // 1) segment average + one-time A prep
    avg_kernel<<<C2d * C1d, 256>>>(x, altx);
    prep_afrag<<<(Md / 16 * 64 + 255) / 256, 256>>>(altx, afrag, Md);

    // 2) s = altx @ weight^T + sin bias; afrag <- LN1(s)   (splitK=16)
    gemm_v2<16><<<dim3(Md / 64, 16), 128>>>(afrag, weight, part, Md, Md);
    reduce_ln<16, F_SIN, 1><<<AVGF, 512>>>(part, nullptr, nullptr, s, afw,
                                           ln1_g, ln1_b);

    for (int a = 0; a < TKd; a++) {
        // qkv partials = y @ Wqkv[a]^T   (N=6144, K=2048, splitK=4)
        gemm_v2<4><<<dim3((3 * Md) / 64, 4), 128>>>(
            afrag, Wqkv + (size_t)a * 3 * Md * Md, part, 3 * Md, Md);

        // fused split-K reduce + attention + cumsum -> afrag(imv)
        attn_fused<4><<<HAd, 128>>>(part, afw);

        // s' = imv @ Wo[a]^T + s;  afrag <- LN2(s') + s'   (splitK=16)
        gemm_v2<16><<<dim3(Md / 64, 16), 128>>>(
            afrag, Wo + (size_t)a * Md * Md, part, Md, Md);
        reduce_ln<16, F_RES, 2><<<AVGF, 512>>>(part, nullptr, s, nullptr, afw,
                                               ln2_g, ln2_b);

        // h partials = s' @ fc1^T  (N=8192, K=2048, splitK=8)
        gemm_v2<8><<<dim3((4 * Md) / 64, 8), 128>>>(afrag, fc1_w, part, 4 * Md, Md);
        // afrag <- gelu(h + b)
        reduce_gelu_frag<8><<<(32 * (4 * Md) / 4 + 127) / 128, 128>>>(
            part, fc1_b, afw, 4 * Md);

        // s = h @ fc2^T + b        (N=2048, K=8192, splitK=16)
        gemm_v2<16><<<dim3(Md / 64, 16), 128>>>(afrag, fc2_w, part, Md, 4 * Md);
        if (a < TKd - 1) {
            // write s raw (residual for next Wo stage) + afrag(LN1(s))
            reduce_ln<16, F_BIAS, 1><<<AVGF, 512>>>(part, fc2_b, nullptr, s, afw,
                                                    ln1_g, ln1_b);
        } else {
            reduce_ln<16, F_BIAS, 0><<<AVGF, 512>>>(part, fc2_b, nullptr, out,
                                                    nullptr, nullptr, nullptr);
        }
    }
}